// round 9
// baseline (speedup 1.0000x reference)
#include <cuda_runtime.h>
#include <cuda_bf16.h>
#include <cuda_fp8.h>
#include <cstdint>

// ---------------------------------------------------------------------------
// Problem constants
// ---------------------------------------------------------------------------
#define QN 16384      // B*N queries
#define DD 256        // dim
#define KK 8192       // codebook size
#define TM 128        // queries per block
#define TN 128        // codes per tile
#define NTILES (KK / TN)          // 64
#define NTHREADS 256
#define QS 16.0f
#define NEG2INV (-2.0f / (QS * QS))   // -2/256
#define RESCORE_T 18.0f
#define INFKEY 0xFF800000FFFFFFFFull

// smem layout (bytes): A 32K | B ring 4x32K | c2 32K = 192KB
#define SM_A 0
#define SM_BRING 32768
#define SM_C2 163840
#define SM_TOTAL 196608

typedef unsigned long long ull;

// ---------------------------------------------------------------------------
// device scratch (static: no allocations allowed)
// ---------------------------------------------------------------------------
__device__ unsigned char g_x_f8[QN * DD];
__device__ unsigned char g_cb_f8[KK * DD];
__device__ float    g_c2[KK];
__device__ unsigned g_idx[QN];

// ---------------------------------------------------------------------------
// PTX helpers
// ---------------------------------------------------------------------------
__device__ __forceinline__ unsigned smem_u32(const void* p) {
    unsigned a;
    asm("{ .reg .u64 t; cvta.to.shared.u64 t, %1; cvt.u32.u64 %0, t; }" : "=r"(a) : "l"(p));
    return a;
}
__device__ __forceinline__ void cp16(unsigned sdst, const void* g) {
    asm volatile("cp.async.cg.shared.global [%0], [%1], 16;" :: "r"(sdst), "l"(g));
}
#define CP_COMMIT() asm volatile("cp.async.commit_group;" ::: "memory")
#define CP_WAIT2()  asm volatile("cp.async.wait_group 2;" ::: "memory")

__device__ __forceinline__ void ldsm4(unsigned* r, unsigned addr) {
    asm volatile("ldmatrix.sync.aligned.m8n8.x4.shared.b16 {%0,%1,%2,%3}, [%4];"
                 : "=r"(r[0]), "=r"(r[1]), "=r"(r[2]), "=r"(r[3]) : "r"(addr));
}
// FP8 e4m3 MMA: D(f32) += A(16x32 e4m3) * B(32x8 e4m3)  [sm_89 legacy form]
__device__ __forceinline__ void fmma16832(float* c, const unsigned* a, const unsigned* b) {
    asm volatile("mma.sync.aligned.m16n8k32.row.col.f32.e4m3.e4m3.f32 "
                 "{%0,%1,%2,%3}, {%4,%5,%6,%7}, {%8,%9}, {%0,%1,%2,%3};"
                 : "+f"(c[0]), "+f"(c[1]), "+f"(c[2]), "+f"(c[3])
                 : "r"(a[0]), "r"(a[1]), "r"(a[2]), "r"(a[3]), "r"(b[0]), "r"(b[1]));
}

__device__ __forceinline__ unsigned f2ord(float f) {
    unsigned u = __float_as_uint(f);
    return (u & 0x80000000u) ? ~u : (u | 0x80000000u);
}
__device__ __forceinline__ float decord(unsigned o) {
    unsigned u = (o & 0x80000000u) ? (o ^ 0x80000000u) : ~o;
    return __uint_as_float(u);
}
__device__ __forceinline__ void upd2(ull& a, ull& b, ull k) {
    if (k < a) { b = a; a = k; } else if (k < b) { b = k; }
}

// ---------------------------------------------------------------------------
// Kernel: fp32 -> e4m3 (scaled by QS) for x and codebook, 16 elems/thread
// ---------------------------------------------------------------------------
__global__ void vq_cvt(const float* __restrict__ x, const float* __restrict__ cb) {
    const int XT = QN * DD / 16, TOT = (QN + KK) * DD / 16;
    int t = blockIdx.x * blockDim.x + threadIdx.x;
    if (t >= TOT) return;
    bool isx = t < XT;
    int o = isx ? t : t - XT;
    const float4* src = (const float4*)(isx ? x : cb) + o * 4;
    uint4 w;
#pragma unroll
    for (int i = 0; i < 4; i++) {
        float4 v = src[i];
        v.x *= QS; v.y *= QS; v.z *= QS; v.w *= QS;
        __nv_fp8x4_e4m3 p(v);
        ((unsigned*)&w)[i] = *reinterpret_cast<unsigned*>(&p);
    }
    ((uint4*)(isx ? g_x_f8 : g_cb_f8))[o] = w;
}

// ---------------------------------------------------------------------------
// Kernel: codebook row norms (one warp per row, exact fp32)
// ---------------------------------------------------------------------------
__global__ void vq_c2k(const float* __restrict__ cb) {
    int w = (blockIdx.x * blockDim.x + threadIdx.x) >> 5;
    int lane = threadIdx.x & 31;
    if (w >= KK) return;
    const float4* r = (const float4*)(cb + (size_t)w * DD);
    float s = 0.f;
#pragma unroll
    for (int j = 0; j < 2; j++) {
        float4 v = r[lane + 32 * j];
        s += v.x * v.x + v.y * v.y + v.z * v.z + v.w * v.w;
    }
#pragma unroll
    for (int o = 16; o; o >>= 1) s += __shfl_xor_sync(0xFFFFFFFFu, s, o);
    if (!lane) g_c2[w] = s;
}

// ---------------------------------------------------------------------------
// Main kernel: FP8 e4m3 GEMM + filtered best-2 argmin + exact fp32 rescore.
// grid = 128 blocks (128 queries each), 256 threads = 8 warps.
// Warp w: m64 rows [(w>>2)*64,+64) x n32 cols [(w&3)*32,+32) per tile.
// A (128x256 e4m3) resident; B 4-deep cp.async ring of 32KB tiles.
// ---------------------------------------------------------------------------
extern __shared__ char dsm[];

__device__ __forceinline__ float dot_exact(const float* a, const float* b) {
    float s0 = 0, s1 = 0, s2 = 0, s3 = 0;
    const float4* A = (const float4*)a;
    const float4* B = (const float4*)b;
#pragma unroll 16
    for (int i = 0; i < DD / 4; i++) {
        float4 u = A[i], w = B[i];
        s0 = fmaf(u.x, w.x, s0); s1 = fmaf(u.y, w.y, s1);
        s2 = fmaf(u.z, w.z, s2); s3 = fmaf(u.w, w.w, s3);
    }
    return (s0 + s1) + (s2 + s3);
}

__global__ void __launch_bounds__(NTHREADS, 1)
vq_main_mma(const float* __restrict__ x, const float* __restrict__ cb) {
    const unsigned sb = smem_u32(dsm);
    const int tid = threadIdx.x;
    const int warp = tid >> 5, lane = tid & 31;
    const int mg = warp >> 2, nw = warp & 3;
    const int qbase = blockIdx.x * TM;

    // ---- B tile load: 128 rows x 256B e4m3 (full k), XOR swizzle ----
    auto issueB = [&](int t) {
        const unsigned stage = sb + SM_BRING + (t & 3) * 32768;
        const unsigned char* src = g_cb_f8 + (size_t)t * TN * DD;
#pragma unroll
        for (int i = 0; i < 8; i++) {
            int l = tid + i * NTHREADS;             // 0..2047 16B units
            int row = l >> 4, u = l & 15;
            int su = (u & 8) | ((u ^ row) & 7);
            cp16(stage + row * 256 + su * 16, src + (size_t)row * DD + u * 16);
        }
    };

    // ---- prologue group: A tile (e4m3, swizzled) + c2 ----
#pragma unroll
    for (int i = 0; i < 8; i++) {
        int l = tid + i * NTHREADS;                 // 0..2047
        int row = l >> 4, u = l & 15;
        int su = (u & 8) | ((u ^ row) & 7);
        cp16(sb + SM_A + row * 256 + su * 16,
             g_x_f8 + (size_t)(qbase + row) * DD + u * 16);
    }
#pragma unroll
    for (int i = 0; i < 8; i++) {
        int l = tid + i * NTHREADS;                 // 0..2047
        cp16(sb + SM_C2 + l * 16, g_c2 + l * 4);
    }
    CP_COMMIT();
    issueB(0); CP_COMMIT();
    issueB(1); CP_COMMIT();
    issueB(2); CP_COMMIT();

    const int a_rowp = (lane & 7) + ((lane >> 3) & 1) * 8;
    const int a_uoff = (lane >> 4) & 1;
    const int b_rowp = (lane & 7) + ((lane >> 4) & 1) * 8;
    const int b_uoff = (lane >> 3) & 1;
    const float* c2s = (const float*)(dsm + SM_C2);

    float acc[4][4][4];
#pragma unroll
    for (int a = 0; a < 4; a++)
#pragma unroll
        for (int b = 0; b < 4; b++)
#pragma unroll
            for (int c = 0; c < 4; c++) acc[a][b][c] = 0.f;

    ull k1[8], k2[8];
    float thr2[8];
#pragma unroll
    for (int i = 0; i < 8; i++) { k1[i] = INFKEY; k2[i] = INFKEY; thr2[i] = 3.4e38f; }

#pragma unroll 1
    for (int t = 0; t < NTILES; t++) {
        CP_WAIT2();                                 // tile t landed (<=2 younger)
        __syncthreads();                            // visible to all; prev compute done
        if (t + 3 < NTILES) issueB(t + 3);
        CP_COMMIT();                                // keep group count uniform

        const unsigned stage = sb + SM_BRING + (t & 3) * 32768;
#pragma unroll
        for (int ks = 0; ks < 8; ks++) {            // k32 per step
            unsigned Bf[2][4];
#pragma unroll
            for (int nt = 0; nt < 2; nt++) {
                int rb = nw * 32 + nt * 16 + b_rowp;
                int u = 2 * ks + b_uoff;
                int su = (u & 8) | ((u ^ rb) & 7);
                ldsm4(Bf[nt], stage + rb * 256 + su * 16);
            }
#pragma unroll
            for (int mt = 0; mt < 4; mt++) {
                int ra = mg * 64 + mt * 16 + a_rowp;
                int u = 2 * ks + a_uoff;
                int su = (u & 8) | ((u ^ ra) & 7);
                unsigned Af[4];
                ldsm4(Af, sb + SM_A + ra * 256 + su * 16);
                fmma16832(acc[mt][0], Af, &Bf[0][0]);
                fmma16832(acc[mt][1], Af, &Bf[0][2]);
                fmma16832(acc[mt][2], Af, &Bf[1][0]);
                fmma16832(acc[mt][3], Af, &Bf[1][2]);
            }
        }

        // ---- filtered epilogue: dist = c2 - (2/QS^2)*dot ----
        float2 cc[4];
#pragma unroll
        for (int jj = 0; jj < 4; jj++)
            cc[jj] = *(const float2*)(c2s + t * TN + nw * 32 + jj * 8 + 2 * (lane & 3));
#pragma unroll
        for (int e = 0; e < 8; e++) {
            const int mt = e >> 1, rh = e & 1;
            float d[8];
#pragma unroll
            for (int jj = 0; jj < 4; jj++) {
                d[2 * jj]     = fmaf(NEG2INV, acc[mt][jj][2 * rh],     cc[jj].x);
                d[2 * jj + 1] = fmaf(NEG2INV, acc[mt][jj][2 * rh + 1], cc[jj].y);
            }
            float m = fminf(fminf(fminf(d[0], d[1]), fminf(d[2], d[3])),
                            fminf(fminf(d[4], d[5]), fminf(d[6], d[7])));
            if (m <= thr2[e]) {                     // rare: could enter best-2
#pragma unroll
                for (int jj = 0; jj < 4; jj++) {
                    const int n0 = t * TN + nw * 32 + jj * 8 + 2 * (lane & 3);
                    upd2(k1[e], k2[e], ((ull)f2ord(d[2 * jj]) << 32) | (unsigned)n0);
                    upd2(k1[e], k2[e], ((ull)f2ord(d[2 * jj + 1]) << 32) | (unsigned)(n0 + 1));
                }
                thr2[e] = decord((unsigned)(k2[e] >> 32));
            }
#pragma unroll
            for (int jj = 0; jj < 4; jj++) {
                acc[mt][jj][2 * rh] = 0.f;
                acc[mt][jj][2 * rh + 1] = 0.f;
            }
        }
    }

    // ---- merge: dump per-lane best-2, reduce per query row ----
    __syncthreads();
    ulonglong2* scr = (ulonglong2*)(dsm + SM_BRING);
#pragma unroll
    for (int e = 0; e < 8; e++)
        scr[tid * 8 + e] = make_ulonglong2(k1[e], k2[e]);
    __syncthreads();

    if (tid < TM) {
        const int row = tid;
        const int mg2 = row >> 6, mt = (row >> 4) & 3, rh = (row >> 3) & 1, lp = row & 7;
        const int e = mt * 2 + rh;
        ull kmin = INFKEY;
#pragma unroll
        for (int nw2 = 0; nw2 < 4; nw2++)
#pragma unroll
            for (int l2 = 0; l2 < 4; l2++) {
                int t2 = (mg2 * 4 + nw2) * 32 + lp * 4 + l2;
                ull v = scr[t2 * 8 + e].x;
                kmin = (v < kmin) ? v : kmin;
            }
        float dmin = decord((unsigned)(kmin >> 32));
        unsigned win = (unsigned)kmin;

        unsigned cand[32]; int nc = 0;
#pragma unroll
        for (int nw2 = 0; nw2 < 4; nw2++)
#pragma unroll
            for (int l2 = 0; l2 < 4; l2++) {
                int t2 = (mg2 * 4 + nw2) * 32 + lp * 4 + l2;
                ulonglong2 v = scr[t2 * 8 + e];
                if (decord((unsigned)(v.x >> 32)) - dmin < RESCORE_T) cand[nc++] = (unsigned)v.x;
                if (decord((unsigned)(v.y >> 32)) - dmin < RESCORE_T) cand[nc++] = (unsigned)v.y;
            }
        if (nc > 1) {
            const float* qv = x + (size_t)(qbase + row) * DD;
            float be = 3.4e38f; unsigned bi = 0xFFFFFFFFu;
            for (int j = 0; j < nc; j++) {
                unsigned i = cand[j];
                float ev = fmaf(-2.f, dot_exact(qv, cb + (size_t)i * DD), c2s[i]);
                if (ev < be || (ev == be && i < bi)) { be = ev; bi = i; }
            }
            win = bi;
        }
        g_idx[qbase + row] = win;
    }
}

// ---------------------------------------------------------------------------
// Output kernel: [x_recon | z_e | z_q | indices(float)]
// ---------------------------------------------------------------------------
__global__ void vq_out(const float* __restrict__ x, const float* __restrict__ cb,
                       float* __restrict__ out, int out_size) {
    const int BND = QN * DD, BND4 = BND / 4;
    int t = blockIdx.x * blockDim.x + threadIdx.x;
    if (t >= BND4) return;
    int q = t >> 6, c4 = t & 63;
    unsigned idx = g_idx[q];
    float4 zq = ((const float4*)cb)[(size_t)idx * (DD / 4) + c4];
    float4 xv = ((const float4*)x)[t];
    float4* o4 = (float4*)out;
    if (out_size >= BND)     o4[t] = zq;
    if (out_size >= 2 * BND) o4[BND4 + t] = xv;
    if (out_size >= 3 * BND) o4[2 * BND4 + t] = zq;
    if (c4 == 0 && out_size >= 3 * BND + QN) out[3 * BND + q] = (float)idx;
}

// ---------------------------------------------------------------------------
extern "C" void kernel_launch(void* const* d_in, const int* in_sizes, int n_in,
                              void* d_out, int out_size) {
    const float* x  = (const float*)d_in[0];
    const float* cb = (const float*)d_in[1];
    float* out = (float*)d_out;

    static int inited = 0;
    if (!inited) {
        cudaFuncSetAttribute(vq_main_mma, cudaFuncAttributeMaxDynamicSharedMemorySize,
                             SM_TOTAL);
        inited = 1;
    }

    const int CVT = (QN + KK) * DD / 16;
    vq_cvt<<<(CVT + 255) / 256, 256>>>(x, cb);
    vq_c2k<<<(KK * 32 + 255) / 256, 256>>>(cb);
    vq_main_mma<<<QN / TM, NTHREADS, SM_TOTAL>>>(x, cb);
    vq_out<<<(QN * DD / 4 + 255) / 256, 256>>>(x, cb, out, out_size);
}

// round 10
// speedup vs baseline: 1.2953x; 1.2953x over previous
#include <cuda_runtime.h>
#include <cuda_bf16.h>
#include <cstdint>

// ---------------------------------------------------------------------------
// Problem constants
// ---------------------------------------------------------------------------
#define QN 16384      // B*N queries
#define DD 256        // dim
#define KK 8192       // codebook size
#define TM 128        // queries per block
#define TN 128        // codes per tile
#define NCHUNK 8      // codebook chunks (grid.x)
#define TPC 8         // tiles per chunk (1024 codes)
#define NTHREADS 256
#define RESCORE_T 2.5f
#define INFKEY 0xFF800000FFFFFFFFull

// smem layout (bytes): A 64K | B ring 2x64K | c2 4K = 196KB+4K
#define SM_A 0
#define SM_BRING 65536
#define SM_C2 196608
#define SM_TOTAL 200704
#define SM_SCR SM_BRING           // merge scratch reuses B ring after loop

typedef unsigned long long ull;

// ---------------------------------------------------------------------------
// device scratch (static: no allocations allowed)
// ---------------------------------------------------------------------------
__device__ __nv_bfloat16 g_x_hi[QN * DD];
__device__ __nv_bfloat16 g_cb_hi[KK * DD];
__device__ float      g_c2[KK];
__device__ unsigned   g_idx[QN];
__device__ ulonglong2 g_part[QN * NCHUNK];   // per-(query,chunk) best-2 keys

// ---------------------------------------------------------------------------
// PTX helpers (sm_80-baseline: legal on plain sm_103 target)
// ---------------------------------------------------------------------------
__device__ __forceinline__ unsigned smem_u32(const void* p) {
    unsigned a;
    asm("{ .reg .u64 t; cvta.to.shared.u64 t, %1; cvt.u32.u64 %0, t; }" : "=r"(a) : "l"(p));
    return a;
}
__device__ __forceinline__ void cp16(unsigned sdst, const void* g) {
    asm volatile("cp.async.cg.shared.global [%0], [%1], 16;" :: "r"(sdst), "l"(g));
}
#define CP_COMMIT() asm volatile("cp.async.commit_group;" ::: "memory")
#define CP_WAIT1()  asm volatile("cp.async.wait_group 1;" ::: "memory")

__device__ __forceinline__ void ldsm4(unsigned* r, unsigned addr) {
    asm volatile("ldmatrix.sync.aligned.m8n8.x4.shared.b16 {%0,%1,%2,%3}, [%4];"
                 : "=r"(r[0]), "=r"(r[1]), "=r"(r[2]), "=r"(r[3]) : "r"(addr));
}
__device__ __forceinline__ void mma16816(float* c, const unsigned* a, const unsigned* b) {
    asm volatile("mma.sync.aligned.m16n8k16.row.col.f32.bf16.bf16.f32 "
                 "{%0,%1,%2,%3}, {%4,%5,%6,%7}, {%8,%9}, {%0,%1,%2,%3};"
                 : "+f"(c[0]), "+f"(c[1]), "+f"(c[2]), "+f"(c[3])
                 : "r"(a[0]), "r"(a[1]), "r"(a[2]), "r"(a[3]), "r"(b[0]), "r"(b[1]));
}

__device__ __forceinline__ unsigned f2ord(float f) {
    unsigned u = __float_as_uint(f);
    return (u & 0x80000000u) ? ~u : (u | 0x80000000u);
}
__device__ __forceinline__ float decord(unsigned o) {
    unsigned u = (o & 0x80000000u) ? (o ^ 0x80000000u) : ~o;
    return __uint_as_float(u);
}
__device__ __forceinline__ void upd2(ull& a, ull& b, ull k) {
    if (k < a) { b = a; a = k; } else if (k < b) { b = k; }
}
__device__ __forceinline__ unsigned pack2(float a, float b) {
    __nv_bfloat162 p = __halves2bfloat162(__float2bfloat16_rn(a), __float2bfloat16_rn(b));
    return *reinterpret_cast<unsigned*>(&p);
}

// ---------------------------------------------------------------------------
// Kernel: fused bf16 convert (x + codebook) and codebook row norms.
// One warp per row; lane loads 32B, packs, stores 16B; cb rows also reduce c2.
// ---------------------------------------------------------------------------
__global__ void vq_prep(const float* __restrict__ x, const float* __restrict__ cb) {
    int w = (blockIdx.x * blockDim.x + threadIdx.x) >> 5;
    int lane = threadIdx.x & 31;
    if (w >= QN + KK) return;
    bool isx = w < QN;
    const float4* src = (const float4*)(isx ? x + (size_t)w * DD
                                            : cb + (size_t)(w - QN) * DD);
    float4 f0 = src[lane * 2], f1 = src[lane * 2 + 1];
    uint4 o;
    o.x = pack2(f0.x, f0.y); o.y = pack2(f0.z, f0.w);
    o.z = pack2(f1.x, f1.y); o.w = pack2(f1.z, f1.w);
    uint4* dst = (uint4*)(isx ? g_x_hi + (size_t)w * DD
                              : g_cb_hi + (size_t)(w - QN) * DD);
    dst[lane] = o;
    if (!isx) {
        float s = f0.x * f0.x + f0.y * f0.y + f0.z * f0.z + f0.w * f0.w
                + f1.x * f1.x + f1.y * f1.y + f1.z * f1.z + f1.w * f1.w;
#pragma unroll
        for (int off = 16; off; off >>= 1) s += __shfl_xor_sync(0xFFFFFFFFu, s, off);
        if (!lane) g_c2[w - QN] = s;
    }
}

// ---------------------------------------------------------------------------
// Main kernel: bf16 GEMM over one codebook chunk (1024 codes) per block.
// grid = (NCHUNK, QN/TM) = 1024 blocks (98.8% SM-slot utilization over 7 waves)
// 256 threads = 8 warps; warp (mg,nw): m64 rows x n32 cols per 128x128 tile.
// Emits per-query best-2 keys of the chunk to g_part.
// ---------------------------------------------------------------------------
extern __shared__ char dsm[];

__global__ void __launch_bounds__(NTHREADS, 1)
vq_main_mma(const float* __restrict__ x, const float* __restrict__ cb) {
    const unsigned sb = smem_u32(dsm);
    const int tid = threadIdx.x;
    const int warp = tid >> 5, lane = tid & 31;
    const int mg = warp >> 2, nw = warp & 3;
    const int qbase = blockIdx.y * TM;
    const int cbase = blockIdx.x * (TPC * TN);     // chunk code offset

    // ---- B tile load: 128 rows x 512B, 16B-unit XOR swizzle ----
    auto issueB = [&](int t) {
        const unsigned stage = sb + SM_BRING + (t & 1) * 65536;
        const __nv_bfloat16* src = g_cb_hi + (size_t)(cbase + t * TN) * DD;
#pragma unroll
        for (int i = 0; i < 16; i++) {
            int unit = tid + i * NTHREADS;          // 0..4095
            int row = unit >> 5, u = unit & 31;
            int su = (u & 24) | ((u ^ row) & 7);
            cp16(stage + row * 512 + (su << 4), src + row * DD + u * 8);
        }
    };

    // ---- resident A (swizzled) + chunk c2 + B tile 0, one cp.async group ----
#pragma unroll
    for (int i = 0; i < 16; i++) {
        int unit = tid + i * NTHREADS;
        int row = unit >> 5, u = unit & 31;
        int su = (u & 24) | ((u ^ row) & 7);
        cp16(sb + SM_A + row * 512 + (su << 4),
             g_x_hi + (size_t)(qbase + row) * DD + u * 8);
    }
    cp16(sb + SM_C2 + tid * 16, g_c2 + cbase + tid * 4);   // 1024 floats
    issueB(0);
    CP_COMMIT();

    // ldmatrix lane address components
    const int a_rowp = (lane & 7) + ((lane >> 3) & 1) * 8;
    const int a_uoff = (lane >> 4) & 1;
    const int b_rowp = (lane & 7) + ((lane >> 4) & 1) * 8;
    const int b_uoff = (lane >> 3) & 1;
    const float* c2s = (const float*)(dsm + SM_C2);

    float acc[4][4][4];
#pragma unroll
    for (int a = 0; a < 4; a++)
#pragma unroll
        for (int b = 0; b < 4; b++)
#pragma unroll
            for (int c = 0; c < 4; c++) acc[a][b][c] = 0.f;

    ull k1[8], k2[8];
    float thr2[8];
#pragma unroll
    for (int i = 0; i < 8; i++) { k1[i] = INFKEY; k2[i] = INFKEY; thr2[i] = 3.4e38f; }

#pragma unroll 1
    for (int t = 0; t < TPC; t++) {
        __syncthreads();                            // buffer (t+1)&1 consumed
        if (t + 1 < TPC) issueB(t + 1);
        CP_COMMIT();
        CP_WAIT1();                                 // tile t landed
        __syncthreads();

        const unsigned stage = sb + SM_BRING + (t & 1) * 65536;
#pragma unroll
        for (int ks = 0; ks < 16; ks++) {
            unsigned Bf[2][4];
#pragma unroll
            for (int nt = 0; nt < 2; nt++) {
                int rb = nw * 32 + nt * 16 + b_rowp;
                int u = 2 * ks + b_uoff;
                int su = (u & 24) | ((u ^ rb) & 7);
                ldsm4(Bf[nt], stage + rb * 512 + (su << 4));
            }
#pragma unroll
            for (int mt = 0; mt < 4; mt++) {
                int ra = mg * 64 + mt * 16 + a_rowp;
                int u = 2 * ks + a_uoff;
                int su = (u & 24) | ((u ^ ra) & 7);
                unsigned Af[4];
                ldsm4(Af, sb + SM_A + ra * 512 + (su << 4));
                mma16816(acc[mt][0], Af, &Bf[0][0]);
                mma16816(acc[mt][1], Af, &Bf[0][2]);
                mma16816(acc[mt][2], Af, &Bf[1][0]);
                mma16816(acc[mt][3], Af, &Bf[1][2]);
            }
        }

        // ---- filtered epilogue (keys carry GLOBAL code index) ----
        float2 cc[4];
#pragma unroll
        for (int jj = 0; jj < 4; jj++)
            cc[jj] = *(const float2*)(c2s + t * TN + nw * 32 + jj * 8 + 2 * (lane & 3));
#pragma unroll
        for (int e = 0; e < 8; e++) {
            const int mt = e >> 1, rh = e & 1;
            float d[8];
#pragma unroll
            for (int jj = 0; jj < 4; jj++) {
                d[2 * jj]     = fmaf(-2.f, acc[mt][jj][2 * rh],     cc[jj].x);
                d[2 * jj + 1] = fmaf(-2.f, acc[mt][jj][2 * rh + 1], cc[jj].y);
            }
            float m = fminf(fminf(fminf(d[0], d[1]), fminf(d[2], d[3])),
                            fminf(fminf(d[4], d[5]), fminf(d[6], d[7])));
            if (m <= thr2[e]) {                     // rare: could enter best-2
#pragma unroll
                for (int jj = 0; jj < 4; jj++) {
                    const int n0 = cbase + t * TN + nw * 32 + jj * 8 + 2 * (lane & 3);
                    upd2(k1[e], k2[e], ((ull)f2ord(d[2 * jj]) << 32) | (unsigned)n0);
                    upd2(k1[e], k2[e], ((ull)f2ord(d[2 * jj + 1]) << 32) | (unsigned)(n0 + 1));
                }
                thr2[e] = decord((unsigned)(k2[e] >> 32));
            }
#pragma unroll
            for (int jj = 0; jj < 4; jj++) {
                acc[mt][jj][2 * rh] = 0.f;
                acc[mt][jj][2 * rh + 1] = 0.f;
            }
        }
    }

    // ---- merge across lanes, then slices; write chunk best-2 per query ----
#pragma unroll
    for (int i = 0; i < 8; i++) {
#pragma unroll
        for (int off = 1; off <= 2; off <<= 1) {
            ull o1 = __shfl_xor_sync(0xFFFFFFFFu, k1[i], off);
            ull o2 = __shfl_xor_sync(0xFFFFFFFFu, k2[i], off);
            ull m2 = (k2[i] < o2) ? k2[i] : o2;
            ull mx = (k1[i] > o1) ? k1[i] : o1;
            k1[i] = (k1[i] < o1) ? k1[i] : o1;
            k2[i] = (mx < m2) ? mx : m2;
        }
    }
    __syncthreads();
    ulonglong2* scr = (ulonglong2*)(dsm + SM_SCR);
#pragma unroll
    for (int e = 0; e < 8; e++)
        scr[tid * 8 + e] = make_ulonglong2(k1[e], k2[e]);
    __syncthreads();

    if (tid < TM) {
        const int row = tid;
        const int mg2 = row >> 6, mt = (row >> 4) & 3, rh = (row >> 3) & 1, lp = row & 7;
        const int e = mt * 2 + rh;
        ull b1 = INFKEY, b2 = INFKEY;
#pragma unroll
        for (int nw2 = 0; nw2 < 4; nw2++) {
            int t2 = (mg2 * 4 + nw2) * 32 + lp * 4;        // lane 0 of the merged group
            ulonglong2 v = scr[t2 * 8 + e];
            upd2(b1, b2, v.x);
            upd2(b1, b2, v.y);
        }
        g_part[(size_t)(qbase + row) * NCHUNK + blockIdx.x] = make_ulonglong2(b1, b2);
    }
}

// ---------------------------------------------------------------------------
// Final merge: 16 keys/query -> argmin with exact fp32 rescore of near-ties
// ---------------------------------------------------------------------------
__global__ void vq_fin(const float* __restrict__ x, const float* __restrict__ cb) {
    int q = blockIdx.x * blockDim.x + threadIdx.x;
    if (q >= QN) return;
    ull keys[2 * NCHUNK];
#pragma unroll
    for (int c = 0; c < NCHUNK; c++) {
        ulonglong2 v = g_part[(size_t)q * NCHUNK + c];
        keys[2 * c] = v.x; keys[2 * c + 1] = v.y;
    }
    ull kmin = keys[0];
#pragma unroll
    for (int i = 1; i < 2 * NCHUNK; i++) kmin = (keys[i] < kmin) ? keys[i] : kmin;
    float dmin = decord((unsigned)(kmin >> 32));
    unsigned win = (unsigned)kmin;

    unsigned cand[2 * NCHUNK]; int nc = 0;
#pragma unroll
    for (int i = 0; i < 2 * NCHUNK; i++)
        if (decord((unsigned)(keys[i] >> 32)) - dmin < RESCORE_T)
            cand[nc++] = (unsigned)keys[i];

    if (nc > 1) {
        const float* qv = x + (size_t)q * DD;
        float be = 3.4e38f; unsigned bi = 0xFFFFFFFFu;
        for (int j = 0; j < nc; j++) {
            unsigned i = cand[j];
            const float* bv = cb + (size_t)i * DD;
            float s0 = 0, s1 = 0, s2 = 0, s3 = 0;
            const float4* A = (const float4*)qv;
            const float4* B = (const float4*)bv;
#pragma unroll 16
            for (int u = 0; u < DD / 4; u++) {
                float4 a = A[u], w = B[u];
                s0 = fmaf(a.x, w.x, s0); s1 = fmaf(a.y, w.y, s1);
                s2 = fmaf(a.z, w.z, s2); s3 = fmaf(a.w, w.w, s3);
            }
            float ev = fmaf(-2.f, (s0 + s1) + (s2 + s3), g_c2[i]);
            if (ev < be || (ev == be && i < bi)) { be = ev; bi = i; }
        }
        win = bi;
    }
    g_idx[q] = win;
}

// ---------------------------------------------------------------------------
// Output kernel: [x_recon | z_e | z_q | indices(float)]
// ---------------------------------------------------------------------------
__global__ void vq_out(const float* __restrict__ x, const float* __restrict__ cb,
                       float* __restrict__ out, int out_size) {
    const int BND = QN * DD, BND4 = BND / 4;
    int t = blockIdx.x * blockDim.x + threadIdx.x;
    if (t >= BND4) return;
    int q = t >> 6, c4 = t & 63;
    unsigned idx = g_idx[q];
    float4 zq = ((const float4*)cb)[(size_t)idx * (DD / 4) + c4];
    float4 xv = ((const float4*)x)[t];
    float4* o4 = (float4*)out;
    if (out_size >= BND)     o4[t] = zq;
    if (out_size >= 2 * BND) o4[BND4 + t] = xv;
    if (out_size >= 3 * BND) o4[2 * BND4 + t] = zq;
    if (c4 == 0 && out_size >= 3 * BND + QN) out[3 * BND + q] = (float)idx;
}

// ---------------------------------------------------------------------------
extern "C" void kernel_launch(void* const* d_in, const int* in_sizes, int n_in,
                              void* d_out, int out_size) {
    const float* x  = (const float*)d_in[0];
    const float* cb = (const float*)d_in[1];
    float* out = (float*)d_out;

    static int inited = 0;
    if (!inited) {
        cudaFuncSetAttribute(vq_main_mma, cudaFuncAttributeMaxDynamicSharedMemorySize,
                             SM_TOTAL);
        inited = 1;
    }

    vq_prep<<<(QN + KK) * 32 / 256, 256>>>(x, cb);
    dim3 grid(NCHUNK, QN / TM);
    vq_main_mma<<<grid, NTHREADS, SM_TOTAL>>>(x, cb);
    vq_fin<<<QN / 256, 256>>>(x, cb);
    vq_out<<<(QN * DD / 4 + 255) / 256, 256>>>(x, cb, out, out_size);
}

// round 11
// speedup vs baseline: 1.3846x; 1.0689x over previous
#include <cuda_runtime.h>
#include <cuda_bf16.h>
#include <cstdint>

// ---------------------------------------------------------------------------
// Problem constants
// ---------------------------------------------------------------------------
#define QN 16384      // B*N queries
#define DD 256        // dim
#define KK 8192       // codebook size
#define TM 128        // queries per block
#define TN 128        // codes per tile
#define NTILES (KK / TN)          // 64
#define NTHREADS 256
#define RESCORE_T 2.5f
#define INFKEY 0xFF800000FFFFFFFFull

// smem layout (bytes): A 64K | B ring 2x64K | c2 32K = 224KB
#define SM_A 0
#define SM_BRING 65536
#define SM_C2 196608
#define SM_TOTAL 229376
#define SM_SCR SM_BRING           // merge scratch reuses B ring after loop

typedef unsigned long long ull;

// ---------------------------------------------------------------------------
// device scratch (static: no allocations allowed)
// ---------------------------------------------------------------------------
__device__ __nv_bfloat16 g_cb_hi[KK * DD];
__device__ float    g_c2[KK];
__device__ unsigned g_idx[QN];

// ---------------------------------------------------------------------------
// PTX helpers (sm_80-baseline: legal on plain sm_103 target)
// ---------------------------------------------------------------------------
__device__ __forceinline__ unsigned smem_u32(const void* p) {
    unsigned a;
    asm("{ .reg .u64 t; cvta.to.shared.u64 t, %1; cvt.u32.u64 %0, t; }" : "=r"(a) : "l"(p));
    return a;
}
__device__ __forceinline__ void cp16(unsigned sdst, const void* g) {
    asm volatile("cp.async.cg.shared.global [%0], [%1], 16;" :: "r"(sdst), "l"(g));
}
#define CP_COMMIT() asm volatile("cp.async.commit_group;" ::: "memory")
#define CP_WAIT1()  asm volatile("cp.async.wait_group 1;" ::: "memory")
#define CP_WAIT0()  asm volatile("cp.async.wait_group 0;" ::: "memory")

__device__ __forceinline__ void ldsm4(unsigned* r, unsigned addr) {
    asm volatile("ldmatrix.sync.aligned.m8n8.x4.shared.b16 {%0,%1,%2,%3}, [%4];"
                 : "=r"(r[0]), "=r"(r[1]), "=r"(r[2]), "=r"(r[3]) : "r"(addr));
}
__device__ __forceinline__ void mma16816(float* c, const unsigned* a, const unsigned* b) {
    asm volatile("mma.sync.aligned.m16n8k16.row.col.f32.bf16.bf16.f32 "
                 "{%0,%1,%2,%3}, {%4,%5,%6,%7}, {%8,%9}, {%0,%1,%2,%3};"
                 : "+f"(c[0]), "+f"(c[1]), "+f"(c[2]), "+f"(c[3])
                 : "r"(a[0]), "r"(a[1]), "r"(a[2]), "r"(a[3]), "r"(b[0]), "r"(b[1]));
}

__device__ __forceinline__ unsigned f2ord(float f) {
    unsigned u = __float_as_uint(f);
    return (u & 0x80000000u) ? ~u : (u | 0x80000000u);
}
__device__ __forceinline__ float decord(unsigned o) {
    unsigned u = (o & 0x80000000u) ? (o ^ 0x80000000u) : ~o;
    return __uint_as_float(u);
}
__device__ __forceinline__ void upd2(ull& a, ull& b, ull k) {
    if (k < a) { b = a; a = k; } else if (k < b) { b = k; }
}
__device__ __forceinline__ unsigned pack2(float a, float b) {
    __nv_bfloat162 p = __halves2bfloat162(__float2bfloat16_rn(a), __float2bfloat16_rn(b));
    return *reinterpret_cast<unsigned*>(&p);
}

// ---------------------------------------------------------------------------
// Kernel: fused codebook bf16 convert + row norms (one warp per cb row)
// ---------------------------------------------------------------------------
__global__ void vq_prep(const float* __restrict__ cb) {
    int w = (blockIdx.x * blockDim.x + threadIdx.x) >> 5;
    int lane = threadIdx.x & 31;
    if (w >= KK) return;
    const float4* src = (const float4*)(cb + (size_t)w * DD);
    float4 f0 = src[lane * 2], f1 = src[lane * 2 + 1];
    uint4 o;
    o.x = pack2(f0.x, f0.y); o.y = pack2(f0.z, f0.w);
    o.z = pack2(f1.x, f1.y); o.w = pack2(f1.z, f1.w);
    ((uint4*)(g_cb_hi + (size_t)w * DD))[lane] = o;
    float s = f0.x * f0.x + f0.y * f0.y + f0.z * f0.z + f0.w * f0.w
            + f1.x * f1.x + f1.y * f1.y + f1.z * f1.z + f1.w * f1.w;
#pragma unroll
    for (int off = 16; off; off >>= 1) s += __shfl_xor_sync(0xFFFFFFFFu, s, off);
    if (!lane) g_c2[w] = s;
}

// ---------------------------------------------------------------------------
// Main kernel: R4's bf16 GEMM (m64n32 warp tiles) with in-block A conversion.
// grid = 128 blocks (128 queries each), 256 threads = 8 warps.
// Warp w: m64 rows [(w>>2)*64, +64), n32 cols [(w&3)*32, +32) of each tile.
// B double-buffered 64KB tiles via cp.async, 1-tile lookahead.
// ---------------------------------------------------------------------------
extern __shared__ char dsm[];

__device__ __forceinline__ float dot_exact(const float* a, const float* b) {
    float s0 = 0, s1 = 0, s2 = 0, s3 = 0;
    const float4* A = (const float4*)a;
    const float4* B = (const float4*)b;
#pragma unroll 16
    for (int i = 0; i < DD / 4; i++) {
        float4 u = A[i], w = B[i];
        s0 = fmaf(u.x, w.x, s0); s1 = fmaf(u.y, w.y, s1);
        s2 = fmaf(u.z, w.z, s2); s3 = fmaf(u.w, w.w, s3);
    }
    return (s0 + s1) + (s2 + s3);
}

__global__ void __launch_bounds__(NTHREADS, 1)
vq_main_mma(const float* __restrict__ x, const float* __restrict__ cb) {
    const unsigned sb = smem_u32(dsm);
    const int tid = threadIdx.x;
    const int warp = tid >> 5, lane = tid & 31;
    const int mg = warp >> 2, nw = warp & 3;
    const int qbase = blockIdx.x * TM;

    // ---- B tile load: 128 rows x 512B, 16B-unit XOR swizzle ----
    auto issueB = [&](int t) {
        const unsigned stage = sb + SM_BRING + (t & 1) * 65536;
        const __nv_bfloat16* src = g_cb_hi + (size_t)t * TN * DD;
#pragma unroll
        for (int i = 0; i < 16; i++) {
            int unit = tid + i * NTHREADS;          // 0..4095
            int row = unit >> 5, u = unit & 31;
            int su = (u & 24) | ((u ^ row) & 7);
            cp16(stage + row * 512 + (su << 4), src + row * DD + u * 8);
        }
    };

    // ---- phase 0: stage fp32 x tile (128KB across both B buffers) + c2 ----
#pragma unroll
    for (int i = 0; i < 32; i++) {
        int l = tid + i * NTHREADS;                 // 0..8191 16B units
        int row = l >> 6, u = l & 63;
        cp16(sb + SM_BRING + row * 1024 + u * 16,
             x + (size_t)(qbase + row) * DD + u * 4);
    }
#pragma unroll
    for (int i = 0; i < 8; i++) {
        int l = i * NTHREADS + tid;                 // 0..2047
        cp16(sb + SM_C2 + l * 16, g_c2 + l * 4);
    }
    CP_COMMIT();
    CP_WAIT0();
    __syncthreads();

    // ---- phase 1: convert x tile to bf16 swizzled A (512B fp32 / thread) ----
    {
        const int row = tid >> 1, half = tid & 1;
        const float4* srcr = (const float4*)(dsm + SM_BRING + row * 1024 + half * 512);
#pragma unroll
        for (int j = 0; j < 16; j++) {
            float4 f0 = srcr[j * 2], f1 = srcr[j * 2 + 1];
            uint4 w;
            w.x = pack2(f0.x, f0.y); w.y = pack2(f0.z, f0.w);
            w.z = pack2(f1.x, f1.y); w.w = pack2(f1.z, f1.w);
            int u = half * 16 + j;
            int su = (u & 24) | ((u ^ row) & 7);
            *(uint4*)(dsm + SM_A + row * 512 + su * 16) = w;
        }
    }
    __syncthreads();

    // ---- phase 2: R4's main pipeline (verbatim) ----
    issueB(0);
    CP_COMMIT();

    const int a_rowp = (lane & 7) + ((lane >> 3) & 1) * 8;
    const int a_uoff = (lane >> 4) & 1;
    const int b_rowp = (lane & 7) + ((lane >> 4) & 1) * 8;
    const int b_uoff = (lane >> 3) & 1;
    const float* c2s = (const float*)(dsm + SM_C2);

    ull k1[8], k2[8];                               // best-2 per covered row
#pragma unroll
    for (int i = 0; i < 8; i++) { k1[i] = INFKEY; k2[i] = INFKEY; }

#pragma unroll 1
    for (int t = 0; t < NTILES; t++) {
        __syncthreads();                            // buffer (t+1)&1 free
        if (t + 1 < NTILES) issueB(t + 1);
        CP_COMMIT();
        CP_WAIT1();                                 // tile t landed
        __syncthreads();

        const unsigned stage = sb + SM_BRING + (t & 1) * 65536;
        float acc[4][4][4];
#pragma unroll
        for (int a = 0; a < 4; a++)
#pragma unroll
            for (int b = 0; b < 4; b++)
#pragma unroll
                for (int c = 0; c < 4; c++) acc[a][b][c] = 0.f;

#pragma unroll
        for (int ks = 0; ks < 16; ks++) {
            unsigned Bf[2][4];
#pragma unroll
            for (int nt = 0; nt < 2; nt++) {
                int rb = nw * 32 + nt * 16 + b_rowp;
                int u = 2 * ks + b_uoff;
                int su = (u & 24) | ((u ^ rb) & 7);
                ldsm4(Bf[nt], stage + rb * 512 + (su << 4));
            }
#pragma unroll
            for (int mt = 0; mt < 4; mt++) {
                int ra = mg * 64 + mt * 16 + a_rowp;
                int u = 2 * ks + a_uoff;
                int su = (u & 24) | ((u ^ ra) & 7);
                unsigned Af[4];
                ldsm4(Af, sb + SM_A + ra * 512 + (su << 4));
                mma16816(acc[mt][0], Af, &Bf[0][0]);
                mma16816(acc[mt][1], Af, &Bf[0][2]);
                mma16816(acc[mt][2], Af, &Bf[1][0]);
                mma16816(acc[mt][3], Af, &Bf[1][2]);
            }
        }

        // ---- per-tile epilogue: fold into per-row best-2 ----
#pragma unroll
        for (int mt = 0; mt < 4; mt++) {
#pragma unroll
            for (int jj = 0; jj < 4; jj++) {
                const int n0 = t * TN + nw * 32 + jj * 8 + 2 * (lane & 3);
                float2 cc = *(const float2*)(c2s + n0);
                float d0 = fmaf(-2.f, acc[mt][jj][0], cc.x);
                float d1 = fmaf(-2.f, acc[mt][jj][1], cc.y);
                float d2 = fmaf(-2.f, acc[mt][jj][2], cc.x);
                float d3 = fmaf(-2.f, acc[mt][jj][3], cc.y);
                upd2(k1[2 * mt],     k2[2 * mt],     ((ull)f2ord(d0) << 32) | (unsigned)n0);
                upd2(k1[2 * mt],     k2[2 * mt],     ((ull)f2ord(d1) << 32) | (unsigned)(n0 + 1));
                upd2(k1[2 * mt + 1], k2[2 * mt + 1], ((ull)f2ord(d2) << 32) | (unsigned)n0);
                upd2(k1[2 * mt + 1], k2[2 * mt + 1], ((ull)f2ord(d3) << 32) | (unsigned)(n0 + 1));
            }
        }
    }

    // ---- merge best-2 across the 4 lanes sharing each row ----
#pragma unroll
    for (int i = 0; i < 8; i++) {
#pragma unroll
        for (int off = 1; off <= 2; off <<= 1) {
            ull o1 = __shfl_xor_sync(0xFFFFFFFFu, k1[i], off);
            ull o2 = __shfl_xor_sync(0xFFFFFFFFu, k2[i], off);
            ull m2 = (k2[i] < o2) ? k2[i] : o2;
            ull mx = (k1[i] > o1) ? k1[i] : o1;
            k1[i] = (k1[i] < o1) ? k1[i] : o1;
            k2[i] = (mx < m2) ? mx : m2;
        }
    }

    __syncthreads();                                // compute fully done
    if ((lane & 3) == 0) {
        ulonglong2* scr = (ulonglong2*)(dsm + SM_SCR);
#pragma unroll
        for (int s = 0; s < 8; s++) {
            int mt = s >> 1, rh = s & 1;
            int row = mg * 64 + mt * 16 + (lane >> 2) + rh * 8;
            scr[row * 4 + nw] = make_ulonglong2(k1[s], k2[s]);
        }
    }
    __syncthreads();

    // ---- final per-query: merge 4 slices (8 cands), rescore near-ties ----
    if (tid < TM) {
        const int row = tid;
        const ulonglong2* scr = (const ulonglong2*)(dsm + SM_SCR);
        ull c8[8];
#pragma unroll
        for (int i = 0; i < 4; i++) {
            ulonglong2 v = scr[row * 4 + i];
            c8[2 * i] = v.x; c8[2 * i + 1] = v.y;
        }
        ull kmin = c8[0];
#pragma unroll
        for (int i = 1; i < 8; i++) kmin = (c8[i] < kmin) ? c8[i] : kmin;
        float dmin = decord((unsigned)(kmin >> 32));
        unsigned win = (unsigned)kmin;

        unsigned cand[8]; int nc = 0;
#pragma unroll
        for (int i = 0; i < 8; i++) {
            float d = decord((unsigned)(c8[i] >> 32));
            if (d - dmin < RESCORE_T) cand[nc++] = (unsigned)c8[i];
        }
        if (nc > 1) {
            const float* qv = x + (size_t)(qbase + row) * DD;
            float be = 3.4e38f; unsigned bi = 0xFFFFFFFFu;
            for (int j = 0; j < nc; j++) {
                unsigned i = cand[j];
                float e = fmaf(-2.f, dot_exact(qv, cb + (size_t)i * DD), c2s[i]);
                if (e < be || (e == be && i < bi)) { be = e; bi = i; }
            }
            win = bi;
        }
        g_idx[qbase + row] = win;
    }
}

// ---------------------------------------------------------------------------
// Output kernel: [x_recon | z_e | z_q | indices(float)]
// ---------------------------------------------------------------------------
__global__ void vq_out(const float* __restrict__ x, const float* __restrict__ cb,
                       float* __restrict__ out, int out_size) {
    const int BND = QN * DD, BND4 = BND / 4;
    int t = blockIdx.x * blockDim.x + threadIdx.x;
    if (t >= BND4) return;
    int q = t >> 6, c4 = t & 63;
    unsigned idx = g_idx[q];
    float4 zq = ((const float4*)cb)[(size_t)idx * (DD / 4) + c4];
    float4 xv = ((const float4*)x)[t];
    float4* o4 = (float4*)out;
    if (out_size >= BND)     o4[t] = zq;
    if (out_size >= 2 * BND) o4[BND4 + t] = xv;
    if (out_size >= 3 * BND) o4[2 * BND4 + t] = zq;
    if (c4 == 0 && out_size >= 3 * BND + QN) out[3 * BND + q] = (float)idx;
}

// ---------------------------------------------------------------------------
extern "C" void kernel_launch(void* const* d_in, const int* in_sizes, int n_in,
                              void* d_out, int out_size) {
    const float* x  = (const float*)d_in[0];
    const float* cb = (const float*)d_in[1];
    float* out = (float*)d_out;

    static int inited = 0;
    if (!inited) {
        cudaFuncSetAttribute(vq_main_mma, cudaFuncAttributeMaxDynamicSharedMemorySize,
                             SM_TOTAL);
        inited = 1;
    }

    vq_prep<<<KK * 32 / 256, 256>>>(cb);
    vq_main_mma<<<QN / TM, NTHREADS, SM_TOTAL>>>(x, cb);
    vq_out<<<(QN * DD / 4 + 255) / 256, 256>>>(x, cb, out, out_size);
}